// round 3
// baseline (speedup 1.0000x reference)
#include <cuda_runtime.h>

#define IMG_H 256
#define IMG_W 256
#define HW    (IMG_H * IMG_W)
#define HW4   (HW / 4)

// accumulators: 0 ssim_sum, 1 absdiff, 2 tv_h, 3 tv_v, 4 hist_absdiff, 5 cos_sum, 6 mask_sum
__device__ double g_acc[8];
__device__ int g_hist[64 * 3 * 64];   // per (img, bin)

__constant__ float c_wg[11] = {
    0.0010283748f, 0.0075987582f, 0.0360007696f, 0.1093606895f, 0.2130055325f,
    0.2660117251f, 0.2130055325f, 0.1093606895f, 0.0360007696f, 0.0075987582f,
    0.0010283748f};

__global__ void k_zero(int nhist) {
    int i = blockIdx.x * 256 + threadIdx.x;
    if (i < nhist) g_hist[i] = 0;
    if (blockIdx.x == 0 && threadIdx.x < 8) g_acc[threadIdx.x] = 0.0;
}

__device__ __forceinline__ float wsum(float v) {
#pragma unroll
    for (int o = 16; o; o >>= 1) v += __shfl_xor_sync(0xffffffffu, v, o);
    return v;
}

// ---- f32x2 packed helpers --------------------------------------------------
__device__ __forceinline__ double pk(float lo, float hi) {
    double r; asm("mov.b64 %0, {%1, %2};" : "=d"(r) : "f"(lo), "f"(hi)); return r;
}
__device__ __forceinline__ void upk(double v, float& lo, float& hi) {
    asm("mov.b64 {%0, %1}, %2;" : "=f"(lo), "=f"(hi) : "d"(v));
}
__device__ __forceinline__ double fma2(double a, double b, double c) {
    double r; asm("fma.rn.f32x2 %0, %1, %2, %3;" : "=d"(r) : "d"(a), "d"(b), "d"(c)); return r;
}
__device__ __forceinline__ double mul2(double a, double b) {
    double r; asm("mul.rn.f32x2 %0, %1, %2;" : "=d"(r) : "d"(a), "d"(b)); return r;
}

// ---------------------------------------------------------------------------
// SSIM + L1 + TV fused tiled kernel, vertical-first streaming conv
// ---------------------------------------------------------------------------
#define TW  32
#define TH  32
#define RAD 5
#define IW  42
#define IH  42
#define VBW 44   // vb row stride (keeps double2/float4 rows 16B aligned)

// pass1: vertical conv for one column c, output rows [o0, o0+NOUT)
template <int NOUT>
__device__ __forceinline__ void pass1v(int o0, int c,
                                       const double* __restrict__ w2,
                                       const float2 (*sdc)[IW],
                                       double (*vbm)[VBW],
                                       double (*vbs)[VBW],
                                       float  (*vbx)[VBW]) {
    double accM[NOUT], accS[NOUT];
    float  accX[NOUT];
#pragma unroll
    for (int o = 0; o < NOUT; o++) { accM[o] = 0; accS[o] = 0; accX[o] = 0.f; }

#pragma unroll
    for (int t = 0; t < NOUT + 10; t++) {
        float2 dc = sdc[o0 + t][c];
        double p  = pk(dc.x, dc.y);         // (d, c)
        double q  = mul2(p, p);             // (d^2, c^2)
        float  x  = dc.x * dc.y;            // d*c
#pragma unroll
        for (int o = 0; o < NOUT; o++) {
            int wi = t - o;
            if (wi >= 0 && wi <= 10) {
                int k = wi < 6 ? wi : 10 - wi;
                accM[o] = fma2(w2[k], p, accM[o]);
                accS[o] = fma2(w2[k], q, accS[o]);
                accX[o] = fmaf(c_wg[wi], x, accX[o]);
            }
        }
    }
#pragma unroll
    for (int o = 0; o < NOUT; o++) {
        vbm[o0 + o][c] = accM[o];
        vbs[o0 + o][c] = accS[o];
        vbx[o0 + o][c] = accX[o];
    }
}

__global__ __launch_bounds__(128) void k_ssim(const float* __restrict__ dz,
                                              const float* __restrict__ cw,
                                              const float* __restrict__ mk) {
    __shared__ __align__(16) float2 sdc[IH][IW];   // (dehaze, clean), masked
    __shared__ __align__(16) double vbm[TH][VBW];  // (m1, m2)   after vertical
    __shared__ __align__(16) double vbs[TH][VBW];  // (s11, s22) after vertical
    __shared__ __align__(16) float  vbx[TH][VBW];  // s12        after vertical
    __shared__ float red[4][4];

    int tid = threadIdx.x;
    int img = blockIdx.z;          // b*3 + c
    int b   = img / 3;
    int x0  = blockIdx.x * TW;
    int y0  = blockIdx.y * TH;
    const float* di = dz + (size_t)img * HW;
    const float* ci = cw + (size_t)img * HW;
    const float* mi = mk + (size_t)b * HW;

    // tile load: (dz*mask, cw*mask), zero padded at image borders
    for (int idx = tid; idx < IH * IW; idx += 128) {
        int r = idx / IW, c = idx - r * IW;
        int gy = y0 + r - RAD, gx = x0 + c - RAD;
        float dv = 0.f, cv = 0.f;
        if ((unsigned)gy < IMG_H && (unsigned)gx < IMG_W) {
            int gi = gy * IMG_W + gx;
            float m = mi[gi];
            dv = di[gi] * m;
            cv = ci[gi] * m;
        }
        sdc[r][c] = make_float2(dv, cv);
    }

    double w2[6];
#pragma unroll
    for (int t = 0; t < 6; t++) w2[t] = pk(c_wg[t], c_wg[t]);
    __syncthreads();

    // ---- pass1: vertical conv, 126 work items = 42 cols x 3 row groups ----
    if (tid < 126) {
        int g = tid / 42, c = tid - g * 42;
        if (g == 0)      pass1v<11>(0,  c, w2, sdc, vbm, vbs, vbx);
        else if (g == 1) pass1v<11>(11, c, w2, sdc, vbm, vbs, vbx);
        else             pass1v<10>(22, c, w2, sdc, vbm, vbs, vbx);
    }
    __syncthreads();

    // ---- pass2: horizontal conv, 128 items = 32 rows x 4 col groups of 8 --
    int row = tid >> 2;
    int j0  = (tid & 3) * 8;

    double accm[8], accs[8];
    float  accx[8];
    {
        double win[18];
#pragma unroll
        for (int t = 0; t < 9; t++) {
            double2 v = *(const double2*)&vbm[row][j0 + 2 * t];
            win[2 * t] = v.x; win[2 * t + 1] = v.y;
        }
#pragma unroll
        for (int jo = 0; jo < 8; jo++) {
            double a = 0;
#pragma unroll
            for (int t = 0; t < 11; t++) a = fma2(w2[t < 6 ? t : 10 - t], win[jo + t], a);
            accm[jo] = a;
        }
#pragma unroll
        for (int t = 0; t < 9; t++) {
            double2 v = *(const double2*)&vbs[row][j0 + 2 * t];
            win[2 * t] = v.x; win[2 * t + 1] = v.y;
        }
#pragma unroll
        for (int jo = 0; jo < 8; jo++) {
            double a = 0;
#pragma unroll
            for (int t = 0; t < 11; t++) a = fma2(w2[t < 6 ? t : 10 - t], win[jo + t], a);
            accs[jo] = a;
        }
    }
    {
        float xw[20];
#pragma unroll
        for (int t = 0; t < 5; t++) *(float4*)&xw[4 * t] = *(const float4*)&vbx[row][j0 + 4 * t];
#pragma unroll
        for (int jo = 0; jo < 8; jo++) {
            float a = 0.f;
#pragma unroll
            for (int t = 0; t < 11; t++) a = fmaf(c_wg[t], xw[jo + t], a);
            accx[jo] = a;
        }
    }

    // ---- epilogue: ssim map + L1 + TV for 8 pixels ----
    const float C1c = 1e-4f, C2c = 9e-4f;
    float a_ssim = 0.f, a_abs = 0.f, a_tvh = 0.f, a_tvv = 0.f;
#pragma unroll
    for (int jo = 0; jo < 8; jo++) {
        float mu1, mu2, e11, e22;
        upk(accm[jo], mu1, mu2);
        upk(accs[jo], e11, e22);
        float e12 = accx[jo];
        float m1s = mu1 * mu1, m2s = mu2 * mu2, m12 = mu1 * mu2;
        float num = (2.f * m12 + C1c) * (2.f * (e12 - m12) + C2c);
        float den = (m1s + m2s + C1c) * ((e11 - m1s) + (e22 - m2s) + C2c);
        a_ssim += num / den;

        float2 dc0 = sdc[row + RAD][j0 + jo + RAD];
        a_abs += fabsf(dc0.x - dc0.y);
        if (x0 + j0 + jo + 1 < IMG_W) {
            float2 dcr = sdc[row + RAD][j0 + jo + RAD + 1];
            a_tvh += fabsf(dc0.x - dcr.x);
        }
        if (y0 + row + 1 < IMG_H) {
            float2 dcd = sdc[row + RAD + 1][j0 + jo + RAD];
            a_tvv += fabsf(dc0.x - dcd.x);
        }
    }

    // block reduce 4 scalars (4 warps)
    int lane = tid & 31, wid = tid >> 5;
    a_ssim = wsum(a_ssim); a_abs = wsum(a_abs);
    a_tvh  = wsum(a_tvh);  a_tvv = wsum(a_tvv);
    if (lane == 0) {
        red[wid][0] = a_ssim; red[wid][1] = a_abs;
        red[wid][2] = a_tvh;  red[wid][3] = a_tvv;
    }
    __syncthreads();
    if (tid < 4) {
        float s = 0.f;
#pragma unroll
        for (int w = 0; w < 4; w++) s += red[w][tid];
        atomicAdd(&g_acc[tid], (double)s);
    }
}

// ---------------------------------------------------------------------------
// histogram: 2 CTAs per (b,c) image accumulate into g_hist
// ---------------------------------------------------------------------------
__global__ __launch_bounds__(256) void k_hist_acc(const float4* __restrict__ gt) {
    __shared__ int sh[8][64];
    int tid = threadIdx.x, wid = tid >> 5;
    for (int i = tid; i < 8 * 64; i += 256) ((int*)sh)[i] = 0;
    __syncthreads();

    int img  = blockIdx.x >> 1;
    int half = blockIdx.x & 1;
    const float4* g = gt + (size_t)img * HW4 + half * (HW4 / 2);
    for (int i = tid; i < HW4 / 2; i += 256) {
        float4 x = g[i];
        float xs[4] = {x.x, x.y, x.z, x.w};
#pragma unroll
        for (int k = 0; k < 4; k++) {
            float v = xs[k] * 2.f - 1.f;
            int idx = (int)floorf((v + 1.f) * 0.5f * 64.f);
            idx = min(63, max(0, idx));
            atomicAdd(&sh[wid][idx], 1);
        }
    }
    __syncthreads();

    if (tid < 64) {
        int tot = 0;
#pragma unroll
        for (int w = 0; w < 8; w++) tot += sh[w][tid];
        atomicAdd(&g_hist[img * 64 + tid], tot);
    }
}

__global__ __launch_bounds__(256) void k_hist_diff(const float* __restrict__ nh, int n) {
    __shared__ float red[8];
    float a = 0.f;
    for (int i = blockIdx.x * 256 + threadIdx.x; i < n; i += gridDim.x * 256)
        a += fabsf(nh[i] - (float)g_hist[i] * (1.f / (float)HW));
    int lane = threadIdx.x & 31, wid = threadIdx.x >> 5;
    a = wsum(a);
    if (lane == 0) red[wid] = a;
    __syncthreads();
    if (threadIdx.x == 0) {
        float s = 0.f;
#pragma unroll
        for (int w = 0; w < 8; w++) s += red[w];
        atomicAdd(&g_acc[4], (double)s);
    }
}

// ---------------------------------------------------------------------------
// cosine / normal loss + mask sum (float4 streaming, rsqrt math)
// ---------------------------------------------------------------------------
__device__ __forceinline__ void cospix(float m, float a0, float a1, float a2,
                                       float g0, float g1, float g2,
                                       float& ac, float& am) {
    float q0 = a0 * m, q1 = a1 * m, q2 = a2 * m;
    float n0 = fmaf(2.f, g0 * m, -1.f) * m;
    float n1 = fmaf(2.f, g1 * m, -1.f) * m;
    float n2 = fmaf(2.f, g2 * m, -1.f) * m;
    float pp = q0 * q0 + q1 * q1 + q2 * q2;
    float nn = n0 * n0 + n1 * n1 + n2 * n2;
    float pn = q0 * n0 + q1 * n1 + q2 * n2;
    float invn = nn > 1e-16f ? rsqrtf(nn) : 1e8f;
    float t = pp > 1e-20f ? pn * rsqrtf(pp) * invn : 0.f;
    ac += 1.f - t;
    am += m;
}

__global__ __launch_bounds__(256) void k_cos(const float4* __restrict__ pr,
                                             const float4* __restrict__ gt,
                                             const float4* __restrict__ mk,
                                             int nitems) {
    __shared__ float red[8][2];
    int stride = gridDim.x * blockDim.x;
    float a_cos = 0.f, a_m = 0.f;

    for (int p = blockIdx.x * blockDim.x + threadIdx.x; p < nitems; p += stride) {
        int b   = p >> 14;       // HW4 = 16384 items per image
        int rem = p & 16383;
        size_t base = (size_t)b * 3 * HW4 + rem;
        float4 m4 = mk[(size_t)b * HW4 + rem];
        float4 p0 = pr[base], p1 = pr[base + HW4], p2 = pr[base + 2 * HW4];
        float4 g0 = gt[base], g1 = gt[base + HW4], g2 = gt[base + 2 * HW4];
        cospix(m4.x, p0.x, p1.x, p2.x, g0.x, g1.x, g2.x, a_cos, a_m);
        cospix(m4.y, p0.y, p1.y, p2.y, g0.y, g1.y, g2.y, a_cos, a_m);
        cospix(m4.z, p0.z, p1.z, p2.z, g0.z, g1.z, g2.z, a_cos, a_m);
        cospix(m4.w, p0.w, p1.w, p2.w, g0.w, g1.w, g2.w, a_cos, a_m);
    }

    int lane = threadIdx.x & 31, wid = threadIdx.x >> 5;
    a_cos = wsum(a_cos); a_m = wsum(a_m);
    if (lane == 0) { red[wid][0] = a_cos; red[wid][1] = a_m; }
    __syncthreads();
    if (threadIdx.x < 2) {
        float s = 0.f;
#pragma unroll
        for (int w = 0; w < 8; w++) s += red[w][threadIdx.x];
        atomicAdd(&g_acc[5 + threadIdx.x], (double)s);
    }
}

// ---------------------------------------------------------------------------
// final combine
// ---------------------------------------------------------------------------
__global__ void k_final(float* __restrict__ out, int B) {
    double N        = (double)B * 3.0 * (double)HW;
    double L_dehaze = g_acc[1] / N;
    double L_ssim   = 1.0 - g_acc[0] / N;
    double cnt_tv   = (double)B * 3.0 * 256.0 * 255.0;
    double L_tv     = g_acc[2] / cnt_tv + g_acc[3] / cnt_tv;
    double L_hist   = g_acc[4] / ((double)B * 3.0 * 64.0);
    double M        = g_acc[6];
    double bg       = (double)B * (double)HW - M;
    double L_normal = (g_acc[5] - bg) / M;
    double total = 10.0 * L_dehaze + L_ssim + L_tv + L_hist + 100.0 * L_normal;
    out[0] = (float)total;
}

// ---------------------------------------------------------------------------
extern "C" void kernel_launch(void* const* d_in, const int* in_sizes, int n_in,
                              void* d_out, int out_size) {
    const float* predict = (const float*)d_in[0];
    const float* gtruth  = (const float*)d_in[1];
    const float* dz      = (const float*)d_in[2];
    const float* cw      = (const float*)d_in[3];
    const float* nh      = (const float*)d_in[4];
    const float* mk      = (const float*)d_in[5];
    int B = in_sizes[0] / (3 * IMG_H * IMG_W);
    int nhist = B * 3 * 64;

    k_zero<<<(nhist + 255) / 256, 256>>>(nhist);

    dim3 gssim(IMG_W / TW, IMG_H / TH, B * 3);
    k_ssim<<<gssim, 128>>>(dz, cw, mk);

    k_hist_acc<<<B * 3 * 2, 256>>>((const float4*)gtruth);
    k_hist_diff<<<12, 256>>>(nh, nhist);

    int nitems = B * HW4;
    k_cos<<<1184, 256>>>((const float4*)predict, (const float4*)gtruth,
                         (const float4*)mk, nitems);

    k_final<<<1, 1>>>((float*)d_out, B);
}